// round 1
// baseline (speedup 1.0000x reference)
#include <cuda_runtime.h>
#include <math.h>

// Problem constants (fixed shapes: x is (4,3,64,64) fp32)
#define HW     4096
#define W64    64
#define NCH    12            // B*C = 4*3
#define NOFF   16129         // 127*127 offsets, dy,dx in [-63,63]
#define NBINS  7939          // d2 in [0, 63^2*2] = [0,7938]
#define SOFF_N 2048          // offsets staged in shared for main kernel

// Persistent scratch (device globals — no allocation)
__device__ int   g_hist[NBINS];
__device__ int   g_start[NBINS];
__device__ int   g_offs[NOFF];    // packed (dy<<16) | (dx & 0xFFFF)
__device__ float g_bound[NCH];

// ---------------------------------------------------------------------------
// K1: zero histogram
__global__ void k_zero() {
    int i = blockIdx.x * blockDim.x + threadIdx.x;
    if (i < NBINS) g_hist[i] = 0;
}

// K2: histogram of squared distances over all offsets
__global__ void k_hist() {
    int i = blockIdx.x * blockDim.x + threadIdx.x;
    if (i >= NOFF) return;
    int dy = i / 127 - 63;
    int dx = i % 127 - 63;
    atomicAdd(&g_hist[dy * dy + dx * dx], 1);
}

// K3: exclusive prefix sum over bins (single block)
__global__ void k_scan() {
    __shared__ int part[256];
    int t = threadIdx.x;
    int base = t * 32;
    int s = 0;
    for (int k = 0; k < 32; ++k) {
        int b = base + k;
        if (b < NBINS) s += g_hist[b];
    }
    part[t] = s;
    __syncthreads();
    if (t == 0) {
        int acc = 0;
        for (int k = 0; k < 256; ++k) { int v = part[k]; part[k] = acc; acc += v; }
    }
    __syncthreads();
    int acc = part[t];
    for (int k = 0; k < 32; ++k) {
        int b = base + k;
        if (b < NBINS) { g_start[b] = acc; acc += g_hist[b]; }
    }
}

// K4: deterministic counting-sort scatter. Rank within a d2-bin = lexicographic
// (dy,dx) rank, computed by enumerating lattice points on the circle.
__global__ void k_scatter() {
    int i = blockIdx.x * blockDim.x + threadIdx.x;
    if (i >= NOFF) return;
    int dy = i / 127 - 63;
    int dx = i % 127 - 63;
    int d2 = dy * dy + dx * dx;
    int rank = 0;
    for (int yy = -63; yy <= 63; ++yy) {
        int rem = d2 - yy * yy;
        if (rem < 0) continue;
        int s = __float2int_rn(sqrtf((float)rem));
        while (s > 0 && s * s > rem) --s;
        while ((s + 1) * (s + 1) <= rem) ++s;
        if (s * s != rem || s > 63) continue;
        // candidate xx = -s
        if (yy < dy || (yy == dy && -s < dx)) ++rank;
        // candidate xx = +s (distinct only when s > 0)
        if (s > 0 && (yy < dy || (yy == dy && s < dx))) ++rank;
    }
    g_offs[g_start[d2] + rank] = (dy << 16) | (dx & 0xFFFF);
}

// K5: per-channel bound = 0.05 * sum(weight)
__global__ void k_bounds(const float* __restrict__ x) {
    __shared__ float red[256];
    int bc = blockIdx.x;
    const float* plane = x + bc * HW;
    float s = 0.f;
    for (int i = threadIdx.x; i < HW; i += 256) s += plane[i];
    red[threadIdx.x] = s;
    __syncthreads();
    for (int st = 128; st > 0; st >>= 1) {
        if (threadIdx.x < st) red[threadIdx.x] += red[threadIdx.x + st];
        __syncthreads();
    }
    if (threadIdx.x == 0) g_bound[bc] = 0.05f * red[0];
}

// K6: main DTM kernel. One thread per pixel, 256 pixels (4 rows) per block,
// 16 blocks per channel. Walk distance-sorted offsets until cum weight >= bound.
__global__ __launch_bounds__(256) void k_main(const float* __restrict__ x,
                                              float* __restrict__ out) {
    __shared__ float sw[HW];
    __shared__ int   soff[SOFF_N];

    int bc  = blockIdx.x >> 4;   // 16 blocks per channel
    int seg = blockIdx.x & 15;
    const float* plane = x + bc * HW;

    // Stage channel weights (16KB) as float4
    for (int i = threadIdx.x; i < HW / 4; i += 256)
        ((float4*)sw)[i] = ((const float4*)plane)[i];
    // Stage the hot prefix of the offset table
    for (int i = threadIdx.x; i < SOFF_N; i += 256)
        soff[i] = g_offs[i];
    __syncthreads();

    float bound = g_bound[bc];
    int p  = seg * 256 + threadIdx.x;
    int pi = p >> 6;
    int pj = p & 63;

    float cw = 0.f, cs = 0.f, val = 0.f;
    bool done = false;

    for (int t = 0; t < NOFF; ++t) {
        int ov = (t < SOFF_N) ? soff[t] : g_offs[t];   // uniform per warp
        int dy = ov >> 16;                  // arithmetic shift: sign-extended
        int dx = (int)(short)(ov & 0xFFFF);
        int ni = pi + dy;
        int nj = pj + dx;
        bool valid = ((unsigned)ni < 64u) & ((unsigned)nj < 64u);
        float w = 0.f;
        if (valid && !done) w = sw[(ni << 6) + nj];    // conflict-free gather
        float d2 = (float)(dy * dy + dx * dx);
        cw += w;
        cs += d2 * w;
        if (!done && cw >= bound) {
            val  = cs + d2 * (bound - cw);
            done = true;
        }
        if (__ballot_sync(0xFFFFFFFFu, !done) == 0u) break;
    }
    if (!done) val = cs;  // unreachable safety (total weight = 20*bound)

    out[bc * HW + p] = sqrtf(val / bound);
}

// ---------------------------------------------------------------------------
extern "C" void kernel_launch(void* const* d_in, const int* in_sizes, int n_in,
                              void* d_out, int out_size) {
    const float* x = (const float*)d_in[0];
    float* out = (float*)d_out;

    k_zero<<<(NBINS + 255) / 256, 256>>>();
    k_hist<<<(NOFF + 255) / 256, 256>>>();
    k_scan<<<1, 256>>>();
    k_scatter<<<(NOFF + 255) / 256, 256>>>();
    k_bounds<<<NCH, 256>>>(x);
    k_main<<<NCH * 16, 256>>>(x, out);
}

// round 3
// speedup vs baseline: 3.5808x; 3.5808x over previous
#include <cuda_runtime.h>
#include <math.h>

// Fixed shapes: x is (4,3,64,64) fp32
#define HW     4096
#define NCH    12            // B*C
#define NOFF   16129         // 127*127 offsets, dy,dx in [-63,63]
#define NBINS  7939          // d2 in [0, 2*63^2]
#define SOFF_N 2048          // offsets staged in shared
#define UNR    16            // inner unroll / ballot period

// ---------------------------------------------------------------------------
// Compile-time distance-sorted offset table (counting sort; within-bin order
// is lexicographic (dy,dx)).
// off[i] packs ((dy*64)+dx) * 65536 | (dx & 0xFFFF); d2[i] = float(dy^2+dx^2).
// NOTE: no left-shifts of negatives (UB pre-C++20, rejected in constexpr).
struct Tables {
    int   off[NOFF];
    float d2[NOFF];
};

constexpr Tables make_tables() {
    Tables t{};
    int hist[NBINS] = {};
    for (int dy = -63; dy <= 63; ++dy)
        for (int dx = -63; dx <= 63; ++dx)
            hist[dy * dy + dx * dx]++;
    int start[NBINS] = {};
    int acc = 0;
    for (int b = 0; b < NBINS; ++b) { start[b] = acc; acc += hist[b]; }
    for (int dy = -63; dy <= 63; ++dy)
        for (int dx = -63; dx <= 63; ++dx) {
            int d2  = dy * dy + dx * dx;
            int pos = start[d2]++;
            int lin = dy * 64 + dx;                 // [-4095, 4095]
            t.off[pos] = lin * 65536 | (dx & 0xFFFF);
            t.d2[pos]  = (float)d2;
        }
    return t;
}

__device__ constexpr Tables g_tab = make_tables();

// ---------------------------------------------------------------------------
// Single fused kernel: 128 threads = 128 consecutive pixels (2 rows).
// 32 blocks per channel, 384 blocks total.
__global__ __launch_bounds__(128) void k_main(const float* __restrict__ x,
                                              float* __restrict__ out) {
    __shared__ float  sw[HW];          // channel weight plane (16KB)
    __shared__ float2 soff[SOFF_N];    // (packed offset bits, d2) (16KB)
    __shared__ float  red[128];

    const int bc  = blockIdx.x >> 5;   // 32 blocks per channel
    const int seg = blockIdx.x & 31;
    const float* __restrict__ plane = x + bc * HW;

    // Stage weights (float4) and accumulate this thread's partial sum.
    float acc = 0.f;
    #pragma unroll
    for (int k = 0; k < 8; ++k) {
        int i = threadIdx.x + k * 128;
        float4 v = ((const float4*)plane)[i];
        ((float4*)sw)[i] = v;
        acc += v.x + v.y + v.z + v.w;
    }
    // Stage offset table prefix.
    #pragma unroll
    for (int k = 0; k < SOFF_N / 128; ++k) {
        int i = threadIdx.x + k * 128;
        soff[i] = make_float2(__int_as_float(g_tab.off[i]), g_tab.d2[i]);
    }
    red[threadIdx.x] = acc;
    __syncthreads();
    #pragma unroll
    for (int st = 64; st > 0; st >>= 1) {
        if (threadIdx.x < st) red[threadIdx.x] += red[threadIdx.x + st];
        __syncthreads();
    }
    const float bound = 0.05f * red[0];

    const int p  = seg * 128 + threadIdx.x;
    const int pj = p & 63;

    float cw = 0.f, cs = 0.f, val = 0.f;
    bool done = false;
    bool warp_alive = true;

    // Hot loop over staged offsets.
    for (int t0 = 0; t0 < SOFF_N && warp_alive; t0 += UNR) {
        #pragma unroll
        for (int k = 0; k < UNR; ++k) {
            float2 e = soff[t0 + k];
            int ov   = __float_as_int(e.x);
            int dx   = (int)(short)ov;          // sign-extend low 16
            int lin  = ov >> 16;                // dy*64 + dx
            int nj   = pj + dx;
            int idx  = p + lin;
            bool act = (!done) & ((unsigned)nj < 64u) & ((unsigned)idx < (unsigned)HW);
            float w  = act ? sw[idx] : 0.f;
            cw += w;
            cs += e.y * w;
            if (!done && cw >= bound) { val = cs + e.y * (bound - cw); done = true; }
        }
        warp_alive = (__ballot_sync(0xFFFFFFFFu, !done) != 0u);
    }

    // Cold tail (essentially never taken for these inputs, kept for safety).
    for (int t0 = SOFF_N; t0 < NOFF && warp_alive; t0 += UNR) {
        #pragma unroll
        for (int k = 0; k < UNR; ++k) {
            int t = t0 + k;
            if (t >= NOFF) break;
            int ov   = g_tab.off[t];
            float d2 = g_tab.d2[t];
            int dx   = (int)(short)ov;
            int lin  = ov >> 16;
            int nj   = pj + dx;
            int idx  = p + lin;
            bool act = (!done) & ((unsigned)nj < 64u) & ((unsigned)idx < (unsigned)HW);
            float w  = act ? sw[idx] : 0.f;
            cw += w;
            cs += d2 * w;
            if (!done && cw >= bound) { val = cs + d2 * (bound - cw); done = true; }
        }
        warp_alive = (__ballot_sync(0xFFFFFFFFu, !done) != 0u);
    }
    if (!done) val = cs;   // unreachable safety (total weight = 20*bound)

    out[bc * HW + p] = sqrtf(val / bound);
}

// ---------------------------------------------------------------------------
extern "C" void kernel_launch(void* const* d_in, const int* in_sizes, int n_in,
                              void* d_out, int out_size) {
    const float* x = (const float*)d_in[0];
    float* out = (float*)d_out;
    k_main<<<NCH * 32, 128>>>(x, out);
}

// round 4
// speedup vs baseline: 4.8017x; 1.3410x over previous
#include <cuda_runtime.h>
#include <math.h>

// Fixed shapes: x is (4,3,64,64) fp32
#define HW      4096
#define NCH     12           // B*C
#define NOFF    16129        // 127*127 offsets, dy,dx in [-63,63]
#define NBINS   7939         // d2 in [0, 2*63^2]
#define SOFF_N  2048         // offsets staged in shared (covers deepest scan ~1634)
#define CH      16           // chunk size (ballot / replay granularity)
#define STRIDE  192          // padded plane row stride (63-wide zero margins)
#define PLANE_F (64 * STRIDE)   // 12288 floats

// ---------------------------------------------------------------------------
// Compile-time distance-sorted offset table (counting sort; within-bin order
// lexicographic (dy,dx)). off[i] = dy*STRIDE + dx (padded-plane linear delta);
// d2[i] = float(dy*dy + dx*dx). No shifts of negatives (constexpr-UB safe).
struct Tables {
    int   off[NOFF];
    float d2[NOFF];
};

constexpr Tables make_tables() {
    Tables t{};
    int hist[NBINS] = {};
    for (int dy = -63; dy <= 63; ++dy)
        for (int dx = -63; dx <= 63; ++dx)
            hist[dy * dy + dx * dx]++;
    int start[NBINS] = {};
    int acc = 0;
    for (int b = 0; b < NBINS; ++b) { start[b] = acc; acc += hist[b]; }
    for (int dy = -63; dy <= 63; ++dy)
        for (int dx = -63; dx <= 63; ++dx) {
            int d2  = dy * dy + dx * dx;
            int pos = start[d2]++;
            t.off[pos] = dy * STRIDE + dx;
            t.d2[pos]  = (float)d2;
        }
    return t;
}

__device__ constexpr Tables g_tab = make_tables();

// Dynamic smem: padded plane (48KB) + offset table (16KB) + reduction (512B)
#define SMEM_BYTES ((PLANE_F + SOFF_N * 2 + 128) * 4)

// ---------------------------------------------------------------------------
// 128 threads = 128 consecutive pixels (2 rows); 32 blocks per channel.
__global__ __launch_bounds__(128) void k_main(const float* __restrict__ x,
                                              float* __restrict__ out) {
    extern __shared__ float smem[];
    float*  swp  = smem;                       // [64][STRIDE], zero margins
    float2* soff = (float2*)(smem + PLANE_F);  // (lin bits, d2)
    float*  red  = smem + PLANE_F + SOFF_N * 2;

    const int bc  = blockIdx.x >> 5;
    const int seg = blockIdx.x & 31;
    const float* __restrict__ plane = x + bc * HW;

    // --- Prologue: zero margins, fill data (disjoint addresses, one sync) ---
    // Margins: per row, float4 indices [0,16) and [32,48). 64*32 = 2048 float4.
    #pragma unroll
    for (int m = threadIdx.x; m < 2048; m += 128) {
        int row = m >> 5, k = m & 31;
        int f4  = row * 48 + (k < 16 ? k : k + 16);
        ((float4*)swp)[f4] = make_float4(0.f, 0.f, 0.f, 0.f);
    }
    // Data: 1024 float4, accumulate per-thread partial sum.
    float acc = 0.f;
    #pragma unroll
    for (int i = threadIdx.x; i < 1024; i += 128) {
        int row = i >> 4, c4 = i & 15;
        float4 v = ((const float4*)plane)[row * 16 + c4];
        ((float4*)swp)[row * 48 + 16 + c4] = v;
        acc += v.x + v.y + v.z + v.w;
    }
    // Offset table prefix.
    #pragma unroll
    for (int i = threadIdx.x; i < SOFF_N; i += 128)
        soff[i] = make_float2(__int_as_float(g_tab.off[i]), g_tab.d2[i]);

    red[threadIdx.x] = acc;
    __syncthreads();
    #pragma unroll
    for (int st = 64; st > 0; st >>= 1) {
        if (threadIdx.x < st) red[threadIdx.x] += red[threadIdx.x + st];
        __syncthreads();
    }
    const float bound = 0.05f * red[0];

    const int p  = seg * 128 + threadIdx.x;
    const int pc = (p >> 6) * STRIDE + 64 + (p & 63);  // padded-plane center

    float cw = 0.f, cs = 0.f, val = 0.f;
    bool done = false;

    // --- Hot loop: chunk sums carry no dependence on cw/done ---
    for (int t0 = 0; t0 < SOFF_N; t0 += CH) {
        float s0 = 0.f, s1 = 0.f, q0 = 0.f, q1 = 0.f;
        #pragma unroll
        for (int k = 0; k < CH; ++k) {
            float2 e = soff[t0 + k];
            int idx  = pc + __float_as_int(e.x);
            float w  = 0.f;
            if ((unsigned)idx < (unsigned)PLANE_F) w = swp[idx];
            if (k & 1) { s1 += w; q1 += e.y * w; }
            else       { s0 += w; q0 += e.y * w; }
        }
        float s16 = s0 + s1, q16 = q0 + q1;

        if (!done && cw + s16 >= bound) {
            // Serial replay of this chunk (executed once per thread).
            float cwl = cw, csl = cs;
            #pragma unroll 1
            for (int k = 0; k < CH; ++k) {
                float2 e = soff[t0 + k];
                int idx  = pc + __float_as_int(e.x);
                float w  = 0.f;
                if ((unsigned)idx < (unsigned)PLANE_F) w = swp[idx];
                cwl += w;
                csl += e.y * w;
                if (cwl >= bound) {
                    val  = csl + e.y * (bound - cwl);
                    done = true;
                    break;
                }
            }
            // ulp mismatch: no crossing in replay -> continue with chunk state
        }
        cw += s16;
        cs += q16;
        if (__ballot_sync(0xFFFFFFFFu, !done) == 0u) break;
    }

    // --- Cold safety tail (never reached for these inputs) ---
    if (__ballot_sync(0xFFFFFFFFu, !done) != 0u) {
        #pragma unroll 1
        for (int t = SOFF_N; t < NOFF && !done; ++t) {
            int lin  = g_tab.off[t];
            float d2 = g_tab.d2[t];
            int idx  = pc + lin;
            float w  = 0.f;
            if ((unsigned)idx < (unsigned)PLANE_F) w = swp[idx];
            cw += w;
            cs += d2 * w;
            if (cw >= bound) { val = cs + d2 * (bound - cw); done = true; }
        }
        if (!done) val = cs;
    }

    out[bc * HW + p] = sqrtf(val / bound);
}

// ---------------------------------------------------------------------------
extern "C" void kernel_launch(void* const* d_in, const int* in_sizes, int n_in,
                              void* d_out, int out_size) {
    const float* x = (const float*)d_in[0];
    float* out = (float*)d_out;
    cudaFuncSetAttribute(k_main, cudaFuncAttributeMaxDynamicSharedMemorySize,
                         SMEM_BYTES);
    k_main<<<NCH * 32, 128, SMEM_BYTES>>>(x, out);
}

// round 5
// speedup vs baseline: 5.2043x; 1.0838x over previous
#include <cuda_runtime.h>
#include <math.h>

// Fixed shapes: x is (4,3,64,64) fp32
#define HW      4096
#define NCH     12
#define NOFF    16129        // 127*127 offsets
#define NBINS   7939
#define SOFF_N  2048         // staged offsets (deepest scan ~1650)
#define CH      16           // chunk size
#define STRIDE  192          // padded plane row stride
#define PLANE_F (64 * STRIDE)

struct Tables {
    int   off[NOFF];   // dy*STRIDE + dx
    float d2[NOFF];
};

constexpr Tables make_tables() {
    Tables t{};
    int hist[NBINS] = {};
    for (int dy = -63; dy <= 63; ++dy)
        for (int dx = -63; dx <= 63; ++dx)
            hist[dy * dy + dx * dx]++;
    int start[NBINS] = {};
    int acc = 0;
    for (int b = 0; b < NBINS; ++b) { start[b] = acc; acc += hist[b]; }
    for (int dy = -63; dy <= 63; ++dy)
        for (int dx = -63; dx <= 63; ++dx) {
            int d2  = dy * dy + dx * dx;
            int pos = start[d2]++;
            t.off[pos] = dy * STRIDE + dx;
            t.d2[pos]  = (float)d2;
        }
    return t;
}

__device__ constexpr Tables g_tab = make_tables();

// smem: plane 48KB + table-as-float4 16KB + reduction 1KB
#define SMEM_BYTES ((PLANE_F + SOFF_N * 2 + 256) * 4)

// 256 threads = 2 threads per pixel, 128 consecutive pixels (2 rows).
// 32 blocks per channel, 384 blocks.
__global__ __launch_bounds__(256) void k_main(const float* __restrict__ x,
                                              float* __restrict__ out) {
    extern __shared__ float smem[];
    float*  swp   = smem;                        // [64][STRIDE], zero margins
    float4* soff4 = (float4*)(smem + PLANE_F);   // (lin0,d20,lin1,d21)
    float2* soff2 = (float2*)soff4;              // scalar view for replay
    float*  red   = smem + PLANE_F + SOFF_N * 2;

    const int tid  = threadIdx.x;
    const int bc   = blockIdx.x >> 5;
    const int seg  = blockIdx.x & 31;
    const int role = tid & 1;                    // A=0: offsets [0,8); B=1: [8,16)
    const float* __restrict__ plane = x + bc * HW;

    // --- Prologue (disjoint smem regions, one sync) ---
    #pragma unroll
    for (int m = tid; m < 2048; m += 256) {      // zero margins
        int row = m >> 5, k = m & 31;
        ((float4*)swp)[row * 48 + (k < 16 ? k : k + 16)] =
            make_float4(0.f, 0.f, 0.f, 0.f);
    }
    float acc = 0.f;
    #pragma unroll
    for (int i = tid; i < 1024; i += 256) {      // data + partial sum
        int row = i >> 4, c4 = i & 15;
        float4 v = ((const float4*)plane)[i];
        ((float4*)swp)[row * 48 + 16 + c4] = v;
        acc += v.x + v.y + v.z + v.w;
    }
    #pragma unroll
    for (int i = tid; i < SOFF_N / 2; i += 256)  // interleaved table
        soff4[i] = make_float4(__int_as_float(g_tab.off[2 * i]), g_tab.d2[2 * i],
                               __int_as_float(g_tab.off[2 * i + 1]), g_tab.d2[2 * i + 1]);
    red[tid] = acc;
    __syncthreads();
    #pragma unroll
    for (int st = 128; st > 0; st >>= 1) {
        if (tid < st) red[tid] += red[tid + st];
        __syncthreads();
    }
    const float bound = 0.05f * red[0];

    const int p  = seg * 128 + (tid >> 1);
    const int pc = (p >> 6) * STRIDE + 64 + (p & 63);

    float cw = 0.f, cs = 0.f, val = 0.f;
    bool done = false;

    // --- Hot loop: each role sums 8 of every 16 offsets; batched loads ---
    for (int t0 = 0; t0 < SOFF_N; t0 += CH) {
        const float4* eP = soff4 + ((t0 >> 1) + role * 4);
        float4 e0 = eP[0], e1 = eP[1], e2 = eP[2], e3 = eP[3];
        int i0 = pc + __float_as_int(e0.x), i1 = pc + __float_as_int(e0.z);
        int i2 = pc + __float_as_int(e1.x), i3 = pc + __float_as_int(e1.z);
        int i4 = pc + __float_as_int(e2.x), i5 = pc + __float_as_int(e2.z);
        int i6 = pc + __float_as_int(e3.x), i7 = pc + __float_as_int(e3.z);
        float w0 = ((unsigned)i0 < (unsigned)PLANE_F) ? swp[i0] : 0.f;
        float w1 = ((unsigned)i1 < (unsigned)PLANE_F) ? swp[i1] : 0.f;
        float w2 = ((unsigned)i2 < (unsigned)PLANE_F) ? swp[i2] : 0.f;
        float w3 = ((unsigned)i3 < (unsigned)PLANE_F) ? swp[i3] : 0.f;
        float w4 = ((unsigned)i4 < (unsigned)PLANE_F) ? swp[i4] : 0.f;
        float w5 = ((unsigned)i5 < (unsigned)PLANE_F) ? swp[i5] : 0.f;
        float w6 = ((unsigned)i6 < (unsigned)PLANE_F) ? swp[i6] : 0.f;
        float w7 = ((unsigned)i7 < (unsigned)PLANE_F) ? swp[i7] : 0.f;
        float s = ((w0 + w1) + (w2 + w3)) + ((w4 + w5) + (w6 + w7));
        float q = ((w0 * e0.y + w1 * e0.w) + (w2 * e1.y + w3 * e1.w))
                + ((w4 * e2.y + w5 * e2.w) + (w6 * e3.y + w7 * e3.w));

        // Combine roles (commutative adds keep A/B bitwise-lockstep).
        float s16 = s + __shfl_xor_sync(0xFFFFFFFFu, s, 1);
        float q16 = q + __shfl_xor_sync(0xFFFFFFFFu, q, 1);

        if (!done && cw + s16 >= bound) {
            // Serial replay of the chunk (once; both roles identically).
            float cwl = cw, csl = cs;
            #pragma unroll 1
            for (int k = 0; k < CH; ++k) {
                float2 e = soff2[t0 + k];
                int idx  = pc + __float_as_int(e.x);
                float w  = ((unsigned)idx < (unsigned)PLANE_F) ? swp[idx] : 0.f;
                cwl += w;
                csl += e.y * w;
                if (cwl >= bound) {
                    val = csl + e.y * (bound - cwl);
                    done = true;
                    break;
                }
            }
        }
        cw += s16;
        cs += q16;
        if (__ballot_sync(0xFFFFFFFFu, !done) == 0u) break;
    }

    // --- Cold safety tail (never reached for these inputs) ---
    if (__ballot_sync(0xFFFFFFFFu, !done) != 0u) {
        #pragma unroll 1
        for (int t = SOFF_N; t < NOFF && !done; ++t) {
            int lin  = g_tab.off[t];
            float d2 = g_tab.d2[t];
            int idx  = pc + lin;
            float w  = ((unsigned)idx < (unsigned)PLANE_F) ? swp[idx] : 0.f;
            cw += w;
            cs += d2 * w;
            if (cw >= bound) { val = cs + d2 * (bound - cw); done = true; }
        }
        if (!done) val = cs;
    }

    if (role == 0) out[bc * HW + p] = sqrtf(val / bound);
}

// ---------------------------------------------------------------------------
extern "C" void kernel_launch(void* const* d_in, const int* in_sizes, int n_in,
                              void* d_out, int out_size) {
    const float* x = (const float*)d_in[0];
    float* out = (float*)d_out;
    cudaFuncSetAttribute(k_main, cudaFuncAttributeMaxDynamicSharedMemorySize,
                         SMEM_BYTES);
    k_main<<<NCH * 32, 256, SMEM_BYTES>>>(x, out);
}

// round 6
// speedup vs baseline: 8.2393x; 1.5832x over previous
#include <cuda_runtime.h>
#include <math.h>

// Fixed shapes: x is (4,3,64,64) fp32
#define HW      4096
#define NCH     12
#define NOFF    16129        // 127*127 offsets
#define NBINS   7939
#define SOFF_N  1024         // staged offsets (deepest scan ~820; tail catches rest)
#define CH      16           // chunk size
#define STRIDE  192          // padded plane row stride
#define PLANE_F (64 * STRIDE)

struct Tables {
    int   off[NOFF];   // dy*STRIDE + dx
    float d2[NOFF];
};

constexpr Tables make_tables() {
    Tables t{};
    int hist[NBINS] = {};
    for (int dy = -63; dy <= 63; ++dy)
        for (int dx = -63; dx <= 63; ++dx)
            hist[dy * dy + dx * dx]++;
    int start[NBINS] = {};
    int acc = 0;
    for (int b = 0; b < NBINS; ++b) { start[b] = acc; acc += hist[b]; }
    for (int dy = -63; dy <= 63; ++dy)
        for (int dx = -63; dx <= 63; ++dx) {
            int d2  = dy * dy + dx * dx;
            int pos = start[d2]++;
            t.off[pos] = dy * STRIDE + dx;
            t.d2[pos]  = (float)d2;
        }
    return t;
}

__device__ constexpr Tables g_tab = make_tables();

// smem: plane 48KB + table-as-float4 8KB + reduction 1KB
#define SMEM_BYTES ((PLANE_F + SOFF_N * 2 + 256) * 4)

// 256 threads = 2 threads per pixel (role A/B), 128 consecutive pixels (2 rows).
// 32 blocks per channel, 384 blocks.
__global__ __launch_bounds__(256) void k_main(const float* __restrict__ x,
                                              float* __restrict__ out) {
    extern __shared__ float smem[];
    float*  swp   = smem;                        // [64][STRIDE], zero margins
    float4* soff4 = (float4*)(smem + PLANE_F);   // (lin0,d20,lin1,d21)
    float2* soff2 = (float2*)soff4;
    float*  red   = smem + PLANE_F + SOFF_N * 2;

    const int tid  = threadIdx.x;
    const int bc   = blockIdx.x >> 5;
    const int seg  = blockIdx.x & 31;
    const int role = tid & 1;                    // A: offsets [0,8) of chunk; B: [8,16)
    const float* __restrict__ plane = x + bc * HW;

    // --- Prologue (disjoint smem regions, one sync) ---
    #pragma unroll
    for (int m = tid; m < 2048; m += 256) {      // zero margins
        int row = m >> 5, k = m & 31;
        ((float4*)swp)[row * 48 + (k < 16 ? k : k + 16)] =
            make_float4(0.f, 0.f, 0.f, 0.f);
    }
    float acc = 0.f;
    #pragma unroll
    for (int i = tid; i < 1024; i += 256) {      // data + partial sum
        int row = i >> 4, c4 = i & 15;
        float4 v = ((const float4*)plane)[i];
        ((float4*)swp)[row * 48 + 16 + c4] = v;
        acc += v.x + v.y + v.z + v.w;
    }
    #pragma unroll
    for (int i = tid; i < SOFF_N / 2; i += 256)  // interleaved table
        soff4[i] = make_float4(__int_as_float(g_tab.off[2 * i]), g_tab.d2[2 * i],
                               __int_as_float(g_tab.off[2 * i + 1]), g_tab.d2[2 * i + 1]);
    red[tid] = acc;
    __syncthreads();
    #pragma unroll
    for (int st = 128; st > 0; st >>= 1) {
        if (tid < st) red[tid] += red[tid + st];
        __syncthreads();
    }
    const float bound = 0.05f * red[0];

    const int p  = seg * 128 + (tid >> 1);
    const int pc = (p >> 6) * STRIDE + 64 + (p & 63);

    float cw   = 0.f;    // total weight of completed chunks (both roles)
    float qacc = 0.f;    // role-local d2-weighted sum of completed chunks
    float cw0  = 0.f, q0 = 0.f;
    int   t_cr = -1;
    bool  done = false;

    // --- Hot loop: record crossing chunk only; resolve later ---
    for (int t0 = 0; t0 < SOFF_N; t0 += 2 * CH) {
        #pragma unroll
        for (int c = 0; c < 2; ++c) {
            int tb = t0 + c * CH;
            const float4* eP = soff4 + ((tb >> 1) + role * 4);
            float4 e0 = eP[0], e1 = eP[1], e2 = eP[2], e3 = eP[3];
            int i0 = pc + __float_as_int(e0.x), i1 = pc + __float_as_int(e0.z);
            int i2 = pc + __float_as_int(e1.x), i3 = pc + __float_as_int(e1.z);
            int i4 = pc + __float_as_int(e2.x), i5 = pc + __float_as_int(e2.z);
            int i6 = pc + __float_as_int(e3.x), i7 = pc + __float_as_int(e3.z);
            float w0 = ((unsigned)i0 < (unsigned)PLANE_F) ? swp[i0] : 0.f;
            float w1 = ((unsigned)i1 < (unsigned)PLANE_F) ? swp[i1] : 0.f;
            float w2 = ((unsigned)i2 < (unsigned)PLANE_F) ? swp[i2] : 0.f;
            float w3 = ((unsigned)i3 < (unsigned)PLANE_F) ? swp[i3] : 0.f;
            float w4 = ((unsigned)i4 < (unsigned)PLANE_F) ? swp[i4] : 0.f;
            float w5 = ((unsigned)i5 < (unsigned)PLANE_F) ? swp[i5] : 0.f;
            float w6 = ((unsigned)i6 < (unsigned)PLANE_F) ? swp[i6] : 0.f;
            float w7 = ((unsigned)i7 < (unsigned)PLANE_F) ? swp[i7] : 0.f;
            float s = ((w0 + w1) + (w2 + w3)) + ((w4 + w5) + (w6 + w7));
            float q = ((w0 * e0.y + w1 * e0.w) + (w2 * e1.y + w3 * e1.w))
                    + ((w4 * e2.y + w5 * e2.w) + (w6 * e3.y + w7 * e3.w));
            float s16 = s + __shfl_xor_sync(0xFFFFFFFFu, s, 1);
            // Predicated crossing record (both roles agree bitwise).
            bool cross = (!done) & (cw + s16 >= bound);
            if (cross) { t_cr = tb; cw0 = cw; q0 = qacc; done = true; }
            cw   += s16;
            qacc += q;
        }
        if (__ballot_sync(0xFFFFFFFFu, !done) == 0u) break;
    }

    // --- Epilogue: combine role-local q, one uniform replay per thread ---
    float qsnap = done ? q0 : qacc;
    float cs0   = qsnap + __shfl_xor_sync(0xFFFFFFFFu, qsnap, 1);
    float cwX   = done ? cw0 : cw;

    float val = 0.f;
    bool  found = false;
    int   t_tail = NOFF;          // default: fully resolved
    if (done) {
        float cwl = cwX, csl = cs0;
        // Batched loads, then short serial prefix (executed once, uniformly).
        float wv[CH], dv[CH];
        #pragma unroll
        for (int k = 0; k < CH; ++k) {
            float2 e = soff2[t_cr + k];
            int idx  = pc + __float_as_int(e.x);
            wv[k] = ((unsigned)idx < (unsigned)PLANE_F) ? swp[idx] : 0.f;
            dv[k] = e.y;
        }
        #pragma unroll
        for (int k = 0; k < CH; ++k) {
            cwl += wv[k];
            csl += dv[k] * wv[k];
            if (!found && cwl >= bound) {
                val = csl + dv[k] * (bound - cwl);
                found = true;
            }
        }
        if (!found) { t_tail = t_cr + CH; cwX = cwl; cs0 = csl; } // ulp slip: continue
    } else {
        t_tail = SOFF_N;          // never crossed in staged range
    }

    // --- Cold exact tail (essentially never taken) ---
    if (t_tail < NOFF) {
        float cwl = cwX, csl = cs0;
        #pragma unroll 1
        for (int t = t_tail; t < NOFF && !found; ++t) {
            int lin  = g_tab.off[t];
            float d2 = g_tab.d2[t];
            int idx  = pc + lin;
            float w  = ((unsigned)idx < (unsigned)PLANE_F) ? swp[idx] : 0.f;
            cwl += w;
            csl += d2 * w;
            if (cwl >= bound) { val = csl + d2 * (bound - cwl); found = true; }
        }
        if (!found) val = csl;
    }

    if (role == 0) out[bc * HW + p] = sqrtf(val / bound);
}

// ---------------------------------------------------------------------------
extern "C" void kernel_launch(void* const* d_in, const int* in_sizes, int n_in,
                              void* d_out, int out_size) {
    const float* x = (const float*)d_in[0];
    float* out = (float*)d_out;
    cudaFuncSetAttribute(k_main, cudaFuncAttributeMaxDynamicSharedMemorySize,
                         SMEM_BYTES);
    k_main<<<NCH * 32, 256, SMEM_BYTES>>>(x, out);
}

// round 7
// speedup vs baseline: 8.3643x; 1.0152x over previous
#include <cuda_runtime.h>
#include <math.h>

// Fixed shapes: x is (4,3,64,64) fp32
#define HW      4096
#define NCH     12
#define NOFF    16129        // 127*127 offsets
#define NBINS   7939
#define SOFF_N  1024         // staged offsets: d2<=~330 -> |dy|,|dx|<=19 < 32 margin
#define CH      16           // chunk size
#define STRIDE  128          // padded plane row stride (32-col zero margins)
#define PLANE_F (64 * STRIDE)   // 8192 floats = 32KB

struct Tables {
    int   off[NOFF];   // dy*STRIDE + dx   (hot path, padded-plane delta)
    float d2[NOFF];
    int   pk[NOFF];    // (dy<<16) | (dx & 0xFFFF)  (cold tail, exact decode)
};

constexpr Tables make_tables() {
    Tables t{};
    int hist[NBINS] = {};
    for (int dy = -63; dy <= 63; ++dy)
        for (int dx = -63; dx <= 63; ++dx)
            hist[dy * dy + dx * dx]++;
    int start[NBINS] = {};
    int acc = 0;
    for (int b = 0; b < NBINS; ++b) { start[b] = acc; acc += hist[b]; }
    for (int dy = -63; dy <= 63; ++dy)
        for (int dx = -63; dx <= 63; ++dx) {
            int d2  = dy * dy + dx * dx;
            int pos = start[d2]++;
            t.off[pos] = dy * STRIDE + dx;
            t.d2[pos]  = (float)d2;
            t.pk[pos]  = dy * 65536 | (dx & 0xFFFF);
        }
    return t;
}

__device__ constexpr Tables g_tab = make_tables();

// Deep-first block order: edge row-pairs (long scans) scheduled in wave 1.
constexpr int mk_seg(int i) { return (i & 1) ? 31 - (i >> 1) : (i >> 1); }
__device__ constexpr int seg_order[32] = {
    mk_seg(0),  mk_seg(1),  mk_seg(2),  mk_seg(3),  mk_seg(4),  mk_seg(5),
    mk_seg(6),  mk_seg(7),  mk_seg(8),  mk_seg(9),  mk_seg(10), mk_seg(11),
    mk_seg(12), mk_seg(13), mk_seg(14), mk_seg(15), mk_seg(16), mk_seg(17),
    mk_seg(18), mk_seg(19), mk_seg(20), mk_seg(21), mk_seg(22), mk_seg(23),
    mk_seg(24), mk_seg(25), mk_seg(26), mk_seg(27), mk_seg(28), mk_seg(29),
    mk_seg(30), mk_seg(31)
};

// smem: plane 32KB + table-as-float4 8KB + reduction 1KB
#define SMEM_BYTES ((PLANE_F + SOFF_N * 2 + 256) * 4)

// 256 threads = 2 threads per pixel (role A/B), 128 consecutive pixels (2 rows).
// 32 blocks per channel, 384 blocks.
__global__ __launch_bounds__(256) void k_main(const float* __restrict__ x,
                                              float* __restrict__ out) {
    extern __shared__ float smem[];
    float*  swp   = smem;                        // [64][STRIDE], zero margins
    float4* soff4 = (float4*)(smem + PLANE_F);   // (lin0,d20,lin1,d21)
    float2* soff2 = (float2*)soff4;
    float*  red   = smem + PLANE_F + SOFF_N * 2;

    const int tid  = threadIdx.x;
    const int bc   = blockIdx.x >> 5;
    const int seg  = seg_order[blockIdx.x & 31];
    const int role = tid & 1;                    // A: offsets [0,8) of chunk; B: [8,16)
    const float* __restrict__ plane = x + bc * HW;

    // --- Prologue (disjoint smem regions, one sync) ---
    #pragma unroll
    for (int m = tid; m < 1024; m += 256) {      // zero margins: 16 f4/row
        int row = m >> 4, k = m & 15;
        ((float4*)swp)[row * 32 + (k < 8 ? k : k + 16)] =
            make_float4(0.f, 0.f, 0.f, 0.f);
    }
    float acc = 0.f;
    #pragma unroll
    for (int i = tid; i < 1024; i += 256) {      // data + partial sum
        int row = i >> 4, c4 = i & 15;
        float4 v = ((const float4*)plane)[i];
        ((float4*)swp)[row * 32 + 8 + c4] = v;
        acc += v.x + v.y + v.z + v.w;
    }
    #pragma unroll
    for (int i = tid; i < SOFF_N / 2; i += 256)  // interleaved table
        soff4[i] = make_float4(__int_as_float(g_tab.off[2 * i]), g_tab.d2[2 * i],
                               __int_as_float(g_tab.off[2 * i + 1]), g_tab.d2[2 * i + 1]);
    red[tid] = acc;
    __syncthreads();
    #pragma unroll
    for (int st = 128; st > 0; st >>= 1) {
        if (tid < st) red[tid] += red[tid + st];
        __syncthreads();
    }
    const float bound = 0.05f * red[0];

    const int p  = seg * 128 + (tid >> 1);
    const int pi = p >> 6, pj = p & 63;
    const int pc = pi * STRIDE + 32 + pj;

    float cw   = 0.f;    // total weight of completed chunks (both roles)
    float qacc = 0.f;    // role-local d2-weighted partial
    float cw0  = 0.f, q0 = 0.f;
    int   t_cr = -1;
    bool  done = false;

    // --- Hot loop: record crossing chunk only; resolve later ---
    for (int t0 = 0; t0 < SOFF_N; t0 += 2 * CH) {
        #pragma unroll
        for (int c = 0; c < 2; ++c) {
            int tb = t0 + c * CH;
            const float4* eP = soff4 + ((tb >> 1) + role * 4);
            float4 e0 = eP[0], e1 = eP[1], e2 = eP[2], e3 = eP[3];
            int i0 = pc + __float_as_int(e0.x), i1 = pc + __float_as_int(e0.z);
            int i2 = pc + __float_as_int(e1.x), i3 = pc + __float_as_int(e1.z);
            int i4 = pc + __float_as_int(e2.x), i5 = pc + __float_as_int(e2.z);
            int i6 = pc + __float_as_int(e3.x), i7 = pc + __float_as_int(e3.z);
            float w0 = ((unsigned)i0 < (unsigned)PLANE_F) ? swp[i0] : 0.f;
            float w1 = ((unsigned)i1 < (unsigned)PLANE_F) ? swp[i1] : 0.f;
            float w2 = ((unsigned)i2 < (unsigned)PLANE_F) ? swp[i2] : 0.f;
            float w3 = ((unsigned)i3 < (unsigned)PLANE_F) ? swp[i3] : 0.f;
            float w4 = ((unsigned)i4 < (unsigned)PLANE_F) ? swp[i4] : 0.f;
            float w5 = ((unsigned)i5 < (unsigned)PLANE_F) ? swp[i5] : 0.f;
            float w6 = ((unsigned)i6 < (unsigned)PLANE_F) ? swp[i6] : 0.f;
            float w7 = ((unsigned)i7 < (unsigned)PLANE_F) ? swp[i7] : 0.f;
            float s = ((w0 + w1) + (w2 + w3)) + ((w4 + w5) + (w6 + w7));
            float q = ((w0 * e0.y + w1 * e0.w) + (w2 * e1.y + w3 * e1.w))
                    + ((w4 * e2.y + w5 * e2.w) + (w6 * e3.y + w7 * e3.w));
            float s16 = s + __shfl_xor_sync(0xFFFFFFFFu, s, 1);
            bool cross = (!done) & (cw + s16 >= bound);
            if (cross) { t_cr = tb; cw0 = cw; q0 = qacc; done = true; }
            cw   += s16;
            qacc += q;
        }
        if (__ballot_sync(0xFFFFFFFFu, !done) == 0u) break;
    }

    // --- Epilogue: combine role-local q, one uniform replay per thread ---
    float qsnap = done ? q0 : qacc;
    float cs0   = qsnap + __shfl_xor_sync(0xFFFFFFFFu, qsnap, 1);
    float cwX   = done ? cw0 : cw;

    float val = 0.f;
    bool  found = false;
    int   t_tail = NOFF;
    if (done) {
        float cwl = cwX, csl = cs0;
        float wv[CH], dv[CH];
        #pragma unroll
        for (int k = 0; k < CH; ++k) {
            float2 e = soff2[t_cr + k];
            int idx  = pc + __float_as_int(e.x);
            wv[k] = ((unsigned)idx < (unsigned)PLANE_F) ? swp[idx] : 0.f;
            dv[k] = e.y;
        }
        #pragma unroll
        for (int k = 0; k < CH; ++k) {
            cwl += wv[k];
            csl += dv[k] * wv[k];
            if (!found && cwl >= bound) {
                val = csl + dv[k] * (bound - cwl);
                found = true;
            }
        }
        if (!found) { t_tail = t_cr + CH; cwX = cwl; cs0 = csl; } // ulp slip
    } else {
        t_tail = SOFF_N;
    }

    // --- Cold exact tail (essentially never taken): global gathers, full range ---
    if (t_tail < NOFF) {
        float cwl = cwX, csl = cs0;
        #pragma unroll 1
        for (int t = t_tail; t < NOFF && !found; ++t) {
            int pk   = g_tab.pk[t];
            float d2 = g_tab.d2[t];
            int dy   = pk >> 16;
            int dx   = (int)(short)(pk & 0xFFFF);
            int ni   = pi + dy, nj = pj + dx;
            float w  = 0.f;
            if (((unsigned)ni < 64u) & ((unsigned)nj < 64u))
                w = plane[ni * 64 + nj];
            cwl += w;
            csl += d2 * w;
            if (cwl >= bound) { val = csl + d2 * (bound - cwl); found = true; }
        }
        if (!found) val = csl;
    }

    if (role == 0) out[bc * HW + p] = sqrtf(val / bound);
}

// ---------------------------------------------------------------------------
extern "C" void kernel_launch(void* const* d_in, const int* in_sizes, int n_in,
                              void* d_out, int out_size) {
    const float* x = (const float*)d_in[0];
    float* out = (float*)d_out;
    cudaFuncSetAttribute(k_main, cudaFuncAttributeMaxDynamicSharedMemorySize,
                         SMEM_BYTES);
    k_main<<<NCH * 32, 256, SMEM_BYTES>>>(x, out);
}